// round 12
// baseline (speedup 1.0000x reference)
#include <cuda_runtime.h>
#include <cstdint>
#include <math.h>

#define MAXN 2000000
#define MAXPART 8192
#define SIM_WARPS 8

__device__ float g_e[MAXN];      // exp(beta*(1+cos)) per row
__device__ float g_w[MAXN];      // sharpened (pre-normalized) weights
__device__ float g_part1[MAXPART];
__device__ float g_part2[MAXPART];

__device__ __forceinline__ void cp16(unsigned int saddr, const void* gaddr) {
    asm volatile("cp.async.cg.shared.global [%0], [%1], 16;"
                 :: "r"(saddr), "l"(gaddr) : "memory");
}
__device__ __forceinline__ void cp_commit() {
    asm volatile("cp.async.commit_group;" ::: "memory");
}
template <int N>
__device__ __forceinline__ void cp_wait() {
    asm volatile("cp.async.wait_group %0;" :: "n"(N) : "memory");
}

// merge two butterfly chains at 'off': lanes with (lane&off)==0 continue chain a,
// others chain b. 2 shfls per merge.
__device__ __forceinline__ float merge2(float a, float b, int off, int lane) {
    float ta = __shfl_xor_sync(0xffffffffu, a, off);
    float tb = __shfl_xor_sync(0xffffffffu, b, off);
    return (lane & off) ? (b + tb) : (a + ta);
}

// ---------------- kernel 1: similarity + exp (the 1 GB pass) ----------------
// warp-per-row, 4 rows/iter. Prefetch via cp.async into per-warp smem ping-pong
// (no register cost in flight) -> 5 blocks/SM, 40 warps.
__global__ __launch_bounds__(256, 5) void k_sim(const float* __restrict__ mem,
                                                int n,
                                                const float* __restrict__ kvec,
                                                const float* __restrict__ beta_p) {
    __shared__ __align__(16) char stage[2][SIM_WARPS][4 * 512];
    __shared__ float smr[256];

    const int lane = threadIdx.x & 31;
    const int wib  = threadIdx.x >> 5;                       // warp in block
    const int warp = (blockIdx.x * blockDim.x + threadIdx.x) >> 5;
    const int nwarps = (gridDim.x * blockDim.x) >> 5;

    // inline key prep: kq = k + 1e-16, knorm = ||kq||
    float4 kv = reinterpret_cast<const float4*>(kvec)[lane];
    kv.x += 1e-16f; kv.y += 1e-16f; kv.z += 1e-16f; kv.w += 1e-16f;
    float kk = kv.x * kv.x;
    kk = fmaf(kv.y, kv.y, kk); kk = fmaf(kv.z, kv.z, kk); kk = fmaf(kv.w, kv.w, kk);
    #pragma unroll
    for (int off = 16; off; off >>= 1) kk += __shfl_xor_sync(0xffffffffu, kk, off);
    const float invknorm = 1.0f / fmaxf(sqrtf(kk), 1e-12f);
    const float beta  = *beta_p;

    // compute lanes 0,8,16,24 handle rows 0,2,1,3 after the merge-tree
    const bool is_cl  = ((lane & 7) == 0);
    const int  myrow  = ((lane >> 3) & 1) * 2 + ((lane >> 4) & 1);

    const long long stride = (long long)nwarps * 4;
    const long long nl = n;

    // per-lane smem base addresses of the two staging buffers
    unsigned int sbuf0 = (unsigned int)__cvta_generic_to_shared(&stage[0][wib][0]) + lane * 16;
    unsigned int sbuf1 = (unsigned int)__cvta_generic_to_shared(&stage[1][wib][0]) + lane * 16;

    // issue a 4-row tile (rows clamped to n-1) into buffer at sbase
    auto issue_tile = [&](long long b, unsigned int sbase) {
        #pragma unroll
        for (int r = 0; r < 4; r++) {
            long long rr = b + r; if (rr >= nl) rr = nl - 1;
            cp16(sbase + r * 512, (const char*)(mem + rr * 128) + lane * 16);
        }
        cp_commit();
    };

    float acc = 0.0f;
    long long base = (long long)warp * 4;

    if (base < nl) {
        issue_tile(base, sbuf0);
        if (base + stride < nl) issue_tile(base + stride, sbuf1);
        else cp_commit();                       // empty group keeps pipeline aligned

        int buf = 0;
        while (true) {
            cp_wait<1>();                       // oldest group (current tile) done

            const char* bp = &stage[buf][wib][0];
            float4 c0 = *reinterpret_cast<const float4*>(bp + 0 * 512 + lane * 16);
            float4 c1 = *reinterpret_cast<const float4*>(bp + 1 * 512 + lane * 16);
            float4 c2 = *reinterpret_cast<const float4*>(bp + 2 * 512 + lane * 16);
            float4 c3 = *reinterpret_cast<const float4*>(bp + 3 * 512 + lane * 16);

            float d0 = c0.x * kv.x; d0 = fmaf(c0.y, kv.y, d0); d0 = fmaf(c0.z, kv.z, d0); d0 = fmaf(c0.w, kv.w, d0);
            float d1 = c1.x * kv.x; d1 = fmaf(c1.y, kv.y, d1); d1 = fmaf(c1.z, kv.z, d1); d1 = fmaf(c1.w, kv.w, d1);
            float d2 = c2.x * kv.x; d2 = fmaf(c2.y, kv.y, d2); d2 = fmaf(c2.z, kv.z, d2); d2 = fmaf(c2.w, kv.w, d2);
            float d3 = c3.x * kv.x; d3 = fmaf(c3.y, kv.y, d3); d3 = fmaf(c3.z, kv.z, d3); d3 = fmaf(c3.w, kv.w, d3);
            float s0 = c0.x * c0.x; s0 = fmaf(c0.y, c0.y, s0); s0 = fmaf(c0.z, c0.z, s0); s0 = fmaf(c0.w, c0.w, s0);
            float s1 = c1.x * c1.x; s1 = fmaf(c1.y, c1.y, s1); s1 = fmaf(c1.z, c1.z, s1); s1 = fmaf(c1.w, c1.w, s1);
            float s2 = c2.x * c2.x; s2 = fmaf(c2.y, c2.y, s2); s2 = fmaf(c2.z, c2.z, s2); s2 = fmaf(c2.w, c2.w, s2);
            float s3 = c3.x * c3.x; s3 = fmaf(c3.y, c3.y, s3); s3 = fmaf(c3.z, c3.z, s3); s3 = fmaf(c3.w, c3.w, s3);

            // merge-tree reduction: 8 chains -> 1 value/lane in 16 shfls
            float m0 = merge2(d0, d1, 16, lane);
            float m1 = merge2(d2, d3, 16, lane);
            float m2 = merge2(s0, s1, 16, lane);
            float m3 = merge2(s2, s3, 16, lane);
            float n0 = merge2(m0, m1, 8, lane);
            float n1 = merge2(m2, m3, 8, lane);
            float q  = merge2(n0, n1, 4, lane);
            q += __shfl_xor_sync(0xffffffffu, q, 2);
            q += __shfl_xor_sync(0xffffffffu, q, 1);
            float qs = __shfl_xor_sync(0xffffffffu, q, 4);   // sumsq onto dot lane

            if (is_cl) {
                long long r = base + myrow;
                if (r < nl) {
                    float cosv = q * rsqrtf(qs) * invknorm;
                    float e = __expf(fmaf(beta, cosv, beta));
                    g_e[r] = e;
                    acc += e;
                }
            }

            // refill the buffer just consumed (LDS values all consumed above,
            // so the cp.async overwrite is safe) or pad with an empty group
            long long nxt2 = base + 2 * stride;
            unsigned int sb = buf ? sbuf1 : sbuf0;
            if (nxt2 < nl) issue_tile(nxt2, sb);
            else cp_commit();

            base += stride;
            buf ^= 1;
            if (base >= nl) break;
        }
        cp_wait<0>();   // drain before exit
    }

    smr[threadIdx.x] = acc;
    __syncthreads();
    for (int s = 128; s; s >>= 1) {
        if (threadIdx.x < s) smr[threadIdx.x] += smr[threadIdx.x + s];
        __syncthreads();
    }
    if (threadIdx.x == 0) g_part1[blockIdx.x] = smr[0];
}

// ---- block-wide deterministic sum of a partials array (same result in every block) ----
__device__ __forceinline__ float block_sum_partials(const float* __restrict__ part, int cnt,
                                                    float* __restrict__ sm /*256 floats*/) {
    float a = 0.f;
    for (int i = threadIdx.x; i < cnt; i += 256) a += part[i];
    sm[threadIdx.x] = a;
    __syncthreads();
    #pragma unroll
    for (int s = 128; s; s >>= 1) {
        if (threadIdx.x < s) sm[threadIdx.x] += sm[threadIdx.x + s];
        __syncthreads();
    }
    float r = sm[0];
    __syncthreads();
    return r;
}

// ---------------- kernel 2: interpolate + shift + sharpen, 4-wide ----------------
__global__ __launch_bounds__(256) void k_shift4(const float* __restrict__ wp, int n4, int n,
                                                int cnt1,
                                                const float* __restrict__ g_p,
                                                const float* __restrict__ s_p,
                                                const float* __restrict__ gamma_p) {
    __shared__ float sm[256];
    const float Se = block_sum_partials(g_part1, cnt1, sm);

    const float gg = *g_p;
    const float s0 = s_p[0], s1 = s_p[1], s2 = s_p[2];
    const float gamma = *gamma_p;
    const float one_m_g = 1.0f - gg;
    const float gs = gg / Se;

    float part = 0.f;
    int i = blockIdx.x * blockDim.x + threadIdx.x;
    if (i < n4) {
        int j = i << 2;
        int jm1 = (j == 0) ? (n - 1) : (j - 1);
        int jp4 = (j + 4 == n) ? 0 : (j + 4);

        float4 E  = reinterpret_cast<const float4*>(g_e)[i];
        float4 W  = reinterpret_cast<const float4*>(wp)[i];
        float em1 = g_e[jm1], ep4 = g_e[jp4];
        float wm1 = wp[jm1],  wp4 = wp[jp4];

        float a0 = fmaf(gs, em1, one_m_g * wm1);
        float a1 = fmaf(gs, E.x, one_m_g * W.x);
        float a2 = fmaf(gs, E.y, one_m_g * W.y);
        float a3 = fmaf(gs, E.z, one_m_g * W.z);
        float a4 = fmaf(gs, E.w, one_m_g * W.w);
        float a5 = fmaf(gs, ep4, one_m_g * wp4);

        float h0 = s0 * a0; h0 = fmaf(s1, a1, h0); h0 = fmaf(s2, a2, h0);
        float h1 = s0 * a1; h1 = fmaf(s1, a2, h1); h1 = fmaf(s2, a3, h1);
        float h2 = s0 * a2; h2 = fmaf(s1, a3, h2); h2 = fmaf(s2, a4, h2);
        float h3 = s0 * a3; h3 = fmaf(s1, a4, h3); h3 = fmaf(s2, a5, h3);

        float4 o;
        o.x = __powf(h0, gamma);
        o.y = __powf(h1, gamma);
        o.z = __powf(h2, gamma);
        o.w = __powf(h3, gamma);
        reinterpret_cast<float4*>(g_w)[i] = o;
        part = (o.x + o.y) + (o.z + o.w);
    }
    sm[threadIdx.x] = part;
    __syncthreads();
    for (int s = 128; s; s >>= 1) {
        if (threadIdx.x < s) sm[threadIdx.x] += sm[threadIdx.x + s];
        __syncthreads();
    }
    if (threadIdx.x == 0) g_part2[blockIdx.x] = sm[0];
}

// scalar fallback (n not divisible by 4)
__global__ __launch_bounds__(256) void k_shift1(const float* __restrict__ wp, int n,
                                                int cnt1,
                                                const float* __restrict__ g_p,
                                                const float* __restrict__ s_p,
                                                const float* __restrict__ gamma_p) {
    __shared__ float sm[256];
    const float Se = block_sum_partials(g_part1, cnt1, sm);

    const float gg = *g_p;
    const float s0 = s_p[0], s1 = s_p[1], s2 = s_p[2];
    const float gamma = *gamma_p;
    const float one_m_g = 1.0f - gg;
    const float gs = gg / Se;

    float part = 0.f;
    int tid = blockIdx.x * blockDim.x + threadIdx.x;
    int ntot = gridDim.x * blockDim.x;
    for (int i = tid; i < n; i += ntot) {
        int im1 = (i == 0) ? (n - 1) : (i - 1);
        int ip1 = (i == n - 1) ? 0 : (i + 1);
        float wgm = fmaf(gs, g_e[im1], one_m_g * wp[im1]);
        float wgc = fmaf(gs, g_e[i],   one_m_g * wp[i]);
        float wgp = fmaf(gs, g_e[ip1], one_m_g * wp[ip1]);
        float wh = s0 * wgm; wh = fmaf(s1, wgc, wh); wh = fmaf(s2, wgp, wh);
        float w = __powf(wh, gamma);
        g_w[i] = w;
        part += w;
    }
    sm[threadIdx.x] = part;
    __syncthreads();
    for (int s = 128; s; s >>= 1) {
        if (threadIdx.x < s) sm[threadIdx.x] += sm[threadIdx.x + s];
        __syncthreads();
    }
    if (threadIdx.x == 0) g_part2[blockIdx.x] = sm[0];
}

// ---------------- kernel 3: normalize ----------------
__global__ __launch_bounds__(256) void k_norm4(float4* __restrict__ out, int n4, int cnt2) {
    __shared__ float sm[256];
    const float Sw = block_sum_partials(g_part2, cnt2, sm);
    const float inv = 1.0f / (Sw + 1e-16f);

    int i = blockIdx.x * blockDim.x + threadIdx.x;
    if (i < n4) {
        float4 v = reinterpret_cast<const float4*>(g_w)[i];
        v.x *= inv; v.y *= inv; v.z *= inv; v.w *= inv;
        out[i] = v;
    }
}

__global__ __launch_bounds__(256) void k_norm1(float* __restrict__ out, int n, int cnt2) {
    __shared__ float sm[256];
    const float Sw = block_sum_partials(g_part2, cnt2, sm);
    const float inv = 1.0f / (Sw + 1e-16f);

    int i = blockIdx.x * blockDim.x + threadIdx.x;
    if (i < n) out[i] = g_w[i] * inv;
}

extern "C" void kernel_launch(void* const* d_in, const int* in_sizes, int n_in,
                              void* d_out, int out_size) {
    // inputs: mem [N,128], k [128], beta [1], g [1], s [3], gamma [1], w_prev [N]
    const float* mem    = (const float*)d_in[0];
    const float* k      = (const float*)d_in[1];
    const float* beta_p = (const float*)d_in[2];
    const float* g_p    = (const float*)d_in[3];
    const float* s_p    = (const float*)d_in[4];
    const float* gamma_p= (const float*)d_in[5];
    const float* wp     = (const float*)d_in[6];
    float* out = (float*)d_out;

    int n = in_sizes[6];  // N rows

    // one resident wave: 148 SMs * 5 blocks/SM = 740 blocks
    const int G1 = 740;

    k_sim<<<G1, 256>>>(mem, n, k, beta_p);

    if ((n & 3) == 0) {
        int n4 = n >> 2;
        int G3 = (n4 + 255) / 256;   // 1954 for n=2e6
        k_shift4<<<G3, 256>>>(wp, n4, n, G1, g_p, s_p, gamma_p);
        k_norm4<<<G3, 256>>>((float4*)out, n4, G3);
    } else {
        int G3 = 2048;
        k_shift1<<<G3, 256>>>(wp, n, G1, g_p, s_p, gamma_p);
        k_norm1<<<(n + 255) / 256, 256>>>(out, n, G3);
    }
}